// round 16
// baseline (speedup 1.0000x reference)
#include <cuda_runtime.h>
#include <cuda_bf16.h>
#include <mma.h>
#include <math.h>
#include <string.h>
#include <stdint.h>

using namespace nvcuda;

// Problem constants
#define NN   32768

typedef __nv_bfloat16 bf16;

// ---------------- scratch (allocation-free: __device__ globals) ----------------
__device__ bf16 g_F0h [NN*512];  __device__ bf16 g_F0l [NN*512];
__device__ bf16 g_H1h [NN*512];  __device__ bf16 g_H1l [NN*512];
__device__ bf16 g_H2h [NN*512];  __device__ bf16 g_H2l [NN*512];
__device__ bf16 g_H3h [NN*512];  __device__ bf16 g_H3l [NN*512];
__device__ bf16 g_G1h [NN*512];  __device__ bf16 g_G1l [NN*512];
__device__ bf16 g_G2h [NN*512];  __device__ bf16 g_G2l [NN*512];
__device__ bf16 g_G3h [NN*512];  __device__ bf16 g_G3l [NN*512];
__device__ bf16 g_F0th[NN*512];  __device__ bf16 g_F0tl[NN*512];
// fp32 scratch
__device__ float g_V  [NN*768];
__device__ float g_Vt [NN*768];
__device__ float g_SL [NN*256];
__device__ float g_SR [NN*256];
__device__ float g_VL [NN*768];
__device__ float g_VR [NN*768];

// converted weights: [Nc][K] bf16 (n-major rows, k contiguous), alpha folded in
#define WTOTAL 1966080
__device__ bf16 g_Whi[WTOTAL];
__device__ bf16 g_Wlo[WTOTAL];

// ---------------- helpers ----------------
__device__ __forceinline__ uint32_t s2u(const void* p) {
    return (uint32_t)__cvta_generic_to_shared(p);
}
__device__ __forceinline__ void cp_async16(uint32_t smem_addr, const void* gptr) {
    asm volatile("cp.async.cg.shared.global [%0], [%1], 16;"
                 :: "r"(smem_addr), "l"(gptr) : "memory");
}
#define CP_COMMIT()   asm volatile("cp.async.commit_group;" ::: "memory")
#define CP_WAIT_ALL() asm volatile("cp.async.wait_group 0;" ::: "memory")

__device__ __forceinline__ void split_bf16(float v, bf16& h, bf16& l) {
    h = __float2bfloat16(v);
    l = __float2bfloat16(v - __bfloat162float(h));
}

// ---------------- wmma split-bf16 GEMM -----------------------------------
// C = act( A[M,K] @ (Whi+Wlo)^T + bias + res )
// A modes:
//   normal: Ahi/Alo bf16 pairs, pure cp.async
//   gated (Av!=null): A[r][k] = Av[r*lda+k] * (Gh+Gl)[(r/3)*512+256+k]
//                     (register-double-buffered LDG->convert->STS)
// C modes: Cf fp32 | Chi/Clo bf16 split | Csc scatter-interleave (+old_fii):
//   out[n*1024 + 256 + 3*col + i] = acc + old_fii[...],  r = 3n+i
// SMEM per stage: AH/AL/BH/BL [128][LDE=40] bf16 = 40960 B; 2 stages.
#define LDE 40
#define STAGE_E 20480
#define GEMM_SMEM 81920

__global__ void __launch_bounds__(256, 2)
gemm_tc(const bf16* __restrict__ Ahi, const bf16* __restrict__ Alo, int lda,
        const float* __restrict__ Av,
        const bf16* __restrict__ Gh, const bf16* __restrict__ Gl,
        const bf16* __restrict__ Bhi, const bf16* __restrict__ Blo, int ldb,
        float* __restrict__ Cf, int ldc,
        bf16* __restrict__ Chi, bf16* __restrict__ Clo, int ldc2,
        float* __restrict__ Csc, const float* __restrict__ old_fii,
        const float* __restrict__ bias,
        const float* __restrict__ res, int ldres,
        int K, int act)
{
    extern __shared__ __align__(16) bf16 smx[];

    const int tid  = threadIdx.x;
    const int wid  = tid >> 5;
    const int wm   = wid & 1;
    const int wn   = wid >> 1;
    const int block_m = blockIdx.y * 128;
    const int block_n = blockIdx.x * 128;

    wmma::fragment<wmma::accumulator, 16, 16, 16, float> acc[4][2];
#pragma unroll
    for (int mi = 0; mi < 4; ++mi)
#pragma unroll
        for (int ni = 0; ni < 2; ++ni)
            wmma::fill_fragment(acc[mi][ni], 0.0f);

    const int nk = K >> 5;

    auto CP_B = [&](int s, int k0) {
        uint32_t bh = s2u(smx) + s * (STAGE_E * 2) + 20480;
        uint32_t bl = bh + 10240;
#pragma unroll
        for (int it = 0; it < 2; ++it) {
            int id = it * 256 + tid, row = id >> 2, c = id & 3;
            uint32_t so = (uint32_t)(row * 80 + c * 16);
            size_t bo = (size_t)(block_n + row) * ldb + k0 + c * 8;
            cp_async16(bh + so, Bhi + bo);
            cp_async16(bl + so, Blo + bo);
        }
    };
    auto CP_A = [&](int s, int k0) {
        uint32_t ah = s2u(smx) + s * (STAGE_E * 2);
        uint32_t al = ah + 10240;
#pragma unroll
        for (int it = 0; it < 2; ++it) {
            int id = it * 256 + tid, row = id >> 2, c = id & 3;
            uint32_t so = (uint32_t)(row * 80 + c * 16);
            size_t ao = (size_t)(block_m + row) * lda + k0 + c * 8;
            cp_async16(ah + so, Ahi + ao);
            cp_async16(al + so, Alo + ao);
        }
    };
    auto COMPUTE = [&](int s) {
        const bf16* AH = smx + s * STAGE_E;
        const bf16* AL = AH + 5120;
        const bf16* BH = AH + 10240;
        const bf16* BL = AH + 15360;
#pragma unroll
        for (int ks = 0; ks < 2; ++ks) {
            const int kofs = ks * 16;
            wmma::fragment<wmma::matrix_a, 16, 16, 16, bf16, wmma::row_major> fah[4], fal[4];
#pragma unroll
            for (int mi = 0; mi < 4; ++mi) {
                wmma::load_matrix_sync(fah[mi], AH + (wm * 64 + mi * 16) * LDE + kofs, LDE);
                wmma::load_matrix_sync(fal[mi], AL + (wm * 64 + mi * 16) * LDE + kofs, LDE);
            }
#pragma unroll
            for (int ni = 0; ni < 2; ++ni) {
                wmma::fragment<wmma::matrix_b, 16, 16, 16, bf16, wmma::col_major> fbh, fbl;
                wmma::load_matrix_sync(fbh, BH + (wn * 32 + ni * 16) * LDE + kofs, LDE);
                wmma::load_matrix_sync(fbl, BL + (wn * 32 + ni * 16) * LDE + kofs, LDE);
#pragma unroll
                for (int mi = 0; mi < 4; ++mi) {
                    wmma::mma_sync(acc[mi][ni], fah[mi], fbh, acc[mi][ni]);
                    wmma::mma_sync(acc[mi][ni], fah[mi], fbl, acc[mi][ni]);
                    wmma::mma_sync(acc[mi][ni], fal[mi], fbh, acc[mi][ni]);
                }
            }
        }
    };

    if (Av == nullptr) {
        // ---- normal mode: pure cp.async mainloop ----
        CP_A(0, 0); CP_B(0, 0);
        CP_COMMIT();
        CP_WAIT_ALL();
        __syncthreads();
        for (int it = 0; it < nk; ++it) {
            if (it + 1 < nk) {
                CP_A((it + 1) & 1, (it + 1) << 5);
                CP_B((it + 1) & 1, (it + 1) << 5);
                CP_COMMIT();
            }
            COMPUTE(it & 1);
            CP_WAIT_ALL();
            __syncthreads();
        }
    } else {
        // ---- gated mode: A = V * (Gh+Gl), register-double-buffered ----
        float4 aR[4];
        uint2  ghR[4], glR[4];
        auto LDG_AG = [&](int k0) {
#pragma unroll
            for (int it = 0; it < 4; ++it) {
                int id = it * 256 + tid, row = id >> 3, c4 = id & 7;
                int r = block_m + row;
                aR[it] = *reinterpret_cast<const float4*>(
                    Av + (size_t)r * lda + k0 + c4 * 4);
                int n = r / 3;
                size_t go = (size_t)n * 512 + 256 + k0 + c4 * 4;
                ghR[it] = *reinterpret_cast<const uint2*>(Gh + go);
                glR[it] = *reinterpret_cast<const uint2*>(Gl + go);
            }
        };
        auto STS_AG = [&](int s) {
            bf16* AH = smx + s * STAGE_E;
            bf16* AL = AH + 5120;
#pragma unroll
            for (int it = 0; it < 4; ++it) {
                int id = it * 256 + tid, row = id >> 3, c4 = id & 7;
                float av[4] = {aR[it].x, aR[it].y, aR[it].z, aR[it].w};
                bf16 gh4[4], gl4[4];
                memcpy(gh4, &ghR[it], 8);
                memcpy(gl4, &glR[it], 8);
#pragma unroll
                for (int q = 0; q < 4; ++q) {
                    float g = __bfloat162float(gh4[q]) + __bfloat162float(gl4[q]);
                    float v = av[q] * g;
                    bf16 h, l; split_bf16(v, h, l);
                    AH[row * LDE + c4 * 4 + q] = h;
                    AL[row * LDE + c4 * 4 + q] = l;
                }
            }
        };
        CP_B(0, 0);
        CP_COMMIT();
        LDG_AG(0);
        STS_AG(0);
        CP_WAIT_ALL();
        __syncthreads();
        for (int it = 0; it < nk; ++it) {
            if (it + 1 < nk) {
                LDG_AG((it + 1) << 5);
                CP_B((it + 1) & 1, (it + 1) << 5);
                CP_COMMIT();
            }
            COMPUTE(it & 1);
            if (it + 1 < nk) STS_AG((it + 1) & 1);
            CP_WAIT_ALL();
            __syncthreads();
        }
    }

    // ---- epilogue: two half-tile passes through SMEM ----
    float* sf = reinterpret_cast<float*>(smx);
    __syncthreads();
#pragma unroll
    for (int pass = 0; pass < 2; ++pass) {
        if (wm == pass) {
#pragma unroll
            for (int mi = 0; mi < 4; ++mi)
#pragma unroll
                for (int ni = 0; ni < 2; ++ni)
                    wmma::store_matrix_sync(sf + (mi * 16) * 128 + wn * 32 + ni * 16,
                                            acc[mi][ni], 128, wmma::mem_row_major);
        }
        __syncthreads();
        for (int i = tid; i < 2048; i += 256) {   // 64 rows x 32 float4
            int r = i >> 5, c4 = (i & 31) * 4;
            float4 v = *reinterpret_cast<float4*>(sf + r * 128 + c4);
            int row = block_m + pass * 64 + r;
            int col = block_n + c4;
            float vv[4] = {v.x, v.y, v.z, v.w};
#pragma unroll
            for (int j = 0; j < 4; ++j) {
                float t = vv[j];
                if (bias) t += bias[col + j];
                if (res)  t += res[(size_t)row * ldres + col + j];
                if (act)  t = t / (1.0f + __expf(-t));
                vv[j] = t;
            }
            if (Cf) {
                float4 o; o.x = vv[0]; o.y = vv[1]; o.z = vv[2]; o.w = vv[3];
                *reinterpret_cast<float4*>(Cf + (size_t)row * ldc + col) = o;
            }
            if (Chi) {
                bf16 h[4], l[4];
#pragma unroll
                for (int j = 0; j < 4; ++j) split_bf16(vv[j], h[j], l[j]);
                *reinterpret_cast<uint2*>(Chi + (size_t)row * ldc2 + col) =
                    *reinterpret_cast<uint2*>(h);
                *reinterpret_cast<uint2*>(Clo + (size_t)row * ldc2 + col) =
                    *reinterpret_cast<uint2*>(l);
            }
            if (Csc) {
                int n = row / 3, ii = row - 3 * n;
                size_t base = (size_t)n * 1024 + 256 + ii;
#pragma unroll
                for (int j = 0; j < 4; ++j) {
                    size_t o = base + 3 * (size_t)(col + j);
                    Csc[o] = vv[j] + old_fii[o];
                }
            }
        }
        __syncthreads();
    }
}

// ---------------- batched weight conversion ----------------------------------
__global__ void convert_w6(const float* w0, const float* w1, const float* w2,
                           const float* w3, const float* w4, const float* w5,
                           bf16* __restrict__ hi, bf16* __restrict__ lo,
                           int K, int Nc, float scale, int stride_e)
{
    int per = K * Nc;
    int gidx = blockIdx.x * blockDim.x + threadIdx.x;
    if (gidx >= 6 * per) return;
    int which = gidx / per;
    int idx = gidx - which * per;
    const float* W;
    switch (which) {
        case 0: W = w0; break;
        case 1: W = w1; break;
        case 2: W = w2; break;
        case 3: W = w3; break;
        case 4: W = w4; break;
        default: W = w5; break;
    }
    int n = idx / K, k = idx % K;
    float v = W[(size_t)k * Nc + n] * scale;
    bf16 h, l; split_bf16(v, h, l);
    size_t o = (size_t)which * stride_e + idx;
    hi[o] = h;
    lo[o] = l;
}

// ---------------- elementwise kernels ----------------
__global__ void prep_kernel(const float* __restrict__ x,
                            bf16* __restrict__ F0h, bf16* __restrict__ F0l,
                            float* __restrict__ V)
{
    const int n = blockIdx.x;
    const int u = threadIdx.x;
    const float* xr = x + (size_t)n * 1024;
    float s  = xr[u];
    float v0 = xr[256 + 3 * u + 0];
    float v1 = xr[256 + 3 * u + 1];
    float v2 = xr[256 + 3 * u + 2];
    float nv = sqrtf(v0 * v0 + v1 * v1 + v2 * v2 + 1e-12f);
    bf16 h, l;
    split_bf16(s,  h, l); F0h[(size_t)n * 512 + u] = h;        F0l[(size_t)n * 512 + u] = l;
    split_bf16(nv, h, l); F0h[(size_t)n * 512 + 256 + u] = h;  F0l[(size_t)n * 512 + 256 + u] = l;
    size_t vb = ((size_t)3 * n) * 256 + u;
    V[vb]       = v0;
    V[vb + 256] = v1;
    V[vb + 512] = v2;
}

// tensor product + resnet(x) + norms; outputs F0t hi/lo + Vt fp32
__global__ void tp_kernel(const float* __restrict__ SL, const float* __restrict__ VL,
                          const float* __restrict__ SR, const float* __restrict__ VR,
                          const float* __restrict__ x, const float* __restrict__ V,
                          const float* __restrict__ tpw,
                          bf16* __restrict__ F0th, bf16* __restrict__ F0tl,
                          float* __restrict__ Vt)
{
    const int n = blockIdx.x;
    const int u = threadIdx.x;
    const size_t b256 = (size_t)n * 256 + u;
    const size_t b512 = (size_t)n * 512 + u;
    const size_t vb   = ((size_t)3 * n) * 256 + u;

    float s1 = SL[b256], s2 = SR[b256];
    float ax = VL[vb], ay = VL[vb + 256], az = VL[vb + 512];
    float bx = VR[vb], by = VR[vb + 256], bz = VR[vb + 512];
    float w0 = tpw[u], w1 = tpw[256 + u], w2 = tpw[512 + u],
          w3 = tpw[768 + u], w4 = tpw[1024 + u];

    const float A0 = 0.44721359549995793f;
    const float A1 = 0.77459666924148340f;
    const float I3 = 0.57735026918962576f;
    const float I6 = 0.40824829046386302f;

    float dot = ax * bx + ay * by + az * bz;
    float t0 = A0 * (w0 * s1 * s2 + w3 * I3 * dot) + x[(size_t)n * 1024 + u];

    float cx = ay * bz - az * by;
    float cy = az * bx - ax * bz;
    float cz = ax * by - ay * bx;
    float k1 = A1 * I3 * w1 * s1;
    float k2 = A1 * I3 * w2 * s2;
    float k4 = A1 * I6 * w4;
    float tx = k1 * bx + k2 * ax + k4 * cx + V[vb];
    float ty = k1 * by + k2 * ay + k4 * cy + V[vb + 256];
    float tz = k1 * bz + k2 * az + k4 * cz + V[vb + 512];

    float nv = sqrtf(tx * tx + ty * ty + tz * tz + 1e-12f);
    bf16 h, l;
    split_bf16(t0, h, l); F0th[b512] = h;        F0tl[b512] = l;
    split_bf16(nv, h, l); F0th[b512 + 256] = h;  F0tl[b512 + 256] = l;
    Vt[vb]       = tx;
    Vt[vb + 256] = ty;
    Vt[vb + 512] = tz;
}

// ---------------- host launch ----------------
struct GArg {
    const bf16 *ah, *al; int lda;
    const float* av; const bf16 *gh, *gl;
    const bf16 *bh, *bl; int ldb;
    float* cf; int ldc;
    bf16 *chi, *clo; int ldc2;
    float* csc; const float* ofii;
    const float *bias, *res; int ldres;
};
static inline void launch_tc(const GArg& a, int M, int Nc, int K, int act)
{
    dim3 grid(Nc / 128, M / 128);
    gemm_tc<<<grid, 256, GEMM_SMEM>>>(a.ah, a.al, a.lda, a.av, a.gh, a.gl,
                                      a.bh, a.bl, a.ldb, a.cf, a.ldc,
                                      a.chi, a.clo, a.ldc2, a.csc, a.ofii,
                                      a.bias, a.res, a.ldres, K, act);
}

extern "C" void kernel_launch(void* const* d_in, const int* in_sizes, int n_in,
                              void* d_out, int out_size)
{
    const float* x       = (const float*)d_in[0];
    const float* old_fii = (const float*)d_in[1];
    const float* ng1_w1 = (const float*)d_in[2];
    const float* ng1_b1 = (const float*)d_in[3];
    const float* ng1_w2 = (const float*)d_in[4];
    const float* ng1_b2 = (const float*)d_in[5];
    const float* ng2_w1 = (const float*)d_in[6];
    const float* ng2_b1 = (const float*)d_in[7];
    const float* ng2_w2 = (const float*)d_in[8];
    const float* ng2_b2 = (const float*)d_in[9];
    const float* ngo_w1 = (const float*)d_in[10];
    const float* ngo_b1 = (const float*)d_in[11];
    const float* ngo_w2 = (const float*)d_in[12];
    const float* ngo_b2 = (const float*)d_in[13];
    const float* lin1_w0 = (const float*)d_in[14];
    const float* lin1_b0 = (const float*)d_in[15];
    const float* lin1_w1 = (const float*)d_in[16];
    const float* lin2_w0 = (const float*)d_in[17];
    const float* lin2_b0 = (const float*)d_in[18];
    const float* lin2_w1 = (const float*)d_in[19];
    const float* lin3_w0 = (const float*)d_in[20];
    const float* lin3_b0 = (const float*)d_in[21];
    const float* lin3_w1 = (const float*)d_in[22];
    const float* tp_w    = (const float*)d_in[23];
    float* out = (float*)d_out;

    cudaFuncSetAttribute(gemm_tc, cudaFuncAttributeMaxDynamicSharedMemorySize, GEMM_SMEM);

    bf16 *F0h,*F0l,*H1h,*H1l,*H2h,*H2l,*H3h,*H3l,*G1h,*G1l,*G2h,*G2l,*G3h,*G3l,
         *F0th,*F0tl,*Whi,*Wlo;
    float *V,*Vt,*SL,*SR,*VL,*VR;
    cudaGetSymbolAddress((void**)&F0h,  g_F0h);  cudaGetSymbolAddress((void**)&F0l,  g_F0l);
    cudaGetSymbolAddress((void**)&H1h,  g_H1h);  cudaGetSymbolAddress((void**)&H1l,  g_H1l);
    cudaGetSymbolAddress((void**)&H2h,  g_H2h);  cudaGetSymbolAddress((void**)&H2l,  g_H2l);
    cudaGetSymbolAddress((void**)&H3h,  g_H3h);  cudaGetSymbolAddress((void**)&H3l,  g_H3l);
    cudaGetSymbolAddress((void**)&G1h,  g_G1h);  cudaGetSymbolAddress((void**)&G1l,  g_G1l);
    cudaGetSymbolAddress((void**)&G2h,  g_G2h);  cudaGetSymbolAddress((void**)&G2l,  g_G2l);
    cudaGetSymbolAddress((void**)&G3h,  g_G3h);  cudaGetSymbolAddress((void**)&G3l,  g_G3l);
    cudaGetSymbolAddress((void**)&F0th, g_F0th); cudaGetSymbolAddress((void**)&F0tl, g_F0tl);
    cudaGetSymbolAddress((void**)&Whi,  g_Whi);  cudaGetSymbolAddress((void**)&Wlo,  g_Wlo);
    cudaGetSymbolAddress((void**)&V,    g_V);
    cudaGetSymbolAddress((void**)&Vt,   g_Vt);
    cudaGetSymbolAddress((void**)&SL,   g_SL);
    cudaGetSymbolAddress((void**)&SR,   g_SR);
    cudaGetSymbolAddress((void**)&VL,   g_VL);
    cudaGetSymbolAddress((void**)&VR,   g_VR);

    const int OB = 262144, OS = 65536;
    const int o_ng1w1 = 0,      o_ng2w1 = OB,     o_ng1w2 = 2*OB,
              o_ng2w2 = 3*OB,   o_ngow1 = 4*OB,   o_ngow2 = 5*OB;
    const int o_l1w0 = 6*OB,        o_l1w1 = 6*OB + OS,   o_l2w0 = 6*OB + 2*OS,
              o_l2w1 = 6*OB + 3*OS, o_l3w0 = 6*OB + 4*OS, o_l3w1 = 6*OB + 5*OS;

    const float inv16 = 0.0625f;

    {
        const int T = 256;
        int nb = (6 * 512 * 512 + T - 1) / T;
        convert_w6<<<nb, T>>>(ng1_w1, ng2_w1, ng1_w2, ng2_w2, ngo_w1, ngo_w2,
                              Whi, Wlo, 512, 512, 1.f, OB);
        int ns = (6 * 256 * 256 + T - 1) / T;
        convert_w6<<<ns, T>>>(lin1_w0, lin1_w1, lin2_w0, lin2_w1, lin3_w0, lin3_w1,
                              Whi + 6 * OB, Wlo + 6 * OB, 256, 256, inv16, OS);
    }

    prep_kernel<<<NN, 256>>>(x, F0h, F0l, V);

    GArg a{};
    a.ldres = 0;

    // Stage 2: NormGate MLPs (left/right) — hi/lo outputs
    a = GArg{}; a.ah=F0h; a.al=F0l; a.lda=512; a.bh=Whi+o_ng1w1; a.bl=Wlo+o_ng1w1; a.ldb=512;
    a.chi=H1h; a.clo=H1l; a.ldc2=512; a.bias=ng1_b1;
    launch_tc(a, NN, 512, 512, 1);
    a.bh=Whi+o_ng2w1; a.bl=Wlo+o_ng2w1; a.chi=H2h; a.clo=H2l; a.bias=ng2_b1;
    launch_tc(a, NN, 512, 512, 1);
    a = GArg{}; a.ah=H1h; a.al=H1l; a.lda=512; a.bh=Whi+o_ng1w2; a.bl=Wlo+o_ng1w2; a.ldb=512;
    a.chi=G1h; a.clo=G1l; a.ldc2=512; a.bias=ng1_b2;
    launch_tc(a, NN, 512, 512, 0);
    a.ah=H2h; a.al=H2l; a.bh=Whi+o_ng2w2; a.bl=Wlo+o_ng2w2; a.chi=G2h; a.clo=G2l; a.bias=ng2_b2;
    launch_tc(a, NN, 512, 512, 0);

    // Stage 4: irrep linears (gate fused into vector-lin A path)
    a = GArg{}; a.ah=G1h; a.al=G1l; a.lda=512; a.bh=Whi+o_l1w0; a.bl=Wlo+o_l1w0; a.ldb=256;
    a.cf=SL; a.ldc=256; a.bias=lin1_b0;
    launch_tc(a, NN, 256, 256, 0);
    a = GArg{}; a.av=V; a.lda=256; a.gh=G1h; a.gl=G1l;
    a.bh=Whi+o_l1w1; a.bl=Wlo+o_l1w1; a.ldb=256; a.cf=VL; a.ldc=256;
    launch_tc(a, 3 * NN, 256, 256, 0);
    a = GArg{}; a.ah=G2h; a.al=G2l; a.lda=512; a.bh=Whi+o_l2w0; a.bl=Wlo+o_l2w0; a.ldb=256;
    a.cf=SR; a.ldc=256; a.bias=lin2_b0;
    launch_tc(a, NN, 256, 256, 0);
    a = GArg{}; a.av=V; a.lda=256; a.gh=G2h; a.gl=G2l;
    a.bh=Whi+o_l2w1; a.bl=Wlo+o_l2w1; a.ldb=256; a.cf=VR; a.ldc=256;
    launch_tc(a, 3 * NN, 256, 256, 0);

    // Stage 5: tensor product + resnet
    tp_kernel<<<NN, 256>>>(SL, VL, SR, VR, x, V, tp_w, F0th, F0tl, Vt);

    // Stage 6: output NormGate
    a = GArg{}; a.ah=F0th; a.al=F0tl; a.lda=512; a.bh=Whi+o_ngow1; a.bl=Wlo+o_ngow1; a.ldb=512;
    a.chi=H3h; a.clo=H3l; a.ldc2=512; a.bias=ngo_b1;
    launch_tc(a, NN, 512, 512, 1);
    a = GArg{}; a.ah=H3h; a.al=H3l; a.lda=512; a.bh=Whi+o_ngow2; a.bl=Wlo+o_ngow2; a.ldb=512;
    a.chi=G3h; a.clo=G3l; a.ldc2=512; a.bias=ngo_b2;
    launch_tc(a, NN, 512, 512, 0);

    // Stage 7: final irrep linear + old_fii residual
    a = GArg{}; a.ah=G3h; a.al=G3l; a.lda=512; a.bh=Whi+o_l3w0; a.bl=Wlo+o_l3w0; a.ldb=256;
    a.cf=out; a.ldc=1024; a.bias=lin3_b0; a.res=old_fii; a.ldres=1024;
    launch_tc(a, NN, 256, 256, 0);
    // vector: gated A (Vt * G3), scatter epilogue with old_fii — no VO3, no final_kernel
    a = GArg{}; a.av=Vt; a.lda=256; a.gh=G3h; a.gl=G3l;
    a.bh=Whi+o_l3w1; a.bl=Wlo+o_l3w1; a.ldb=256; a.csc=out; a.ofii=old_fii;
    launch_tc(a, 3 * NN, 256, 256, 0);
}

// round 17
// speedup vs baseline: 1.0238x; 1.0238x over previous
#include <cuda_runtime.h>
#include <cuda_bf16.h>
#include <mma.h>
#include <math.h>
#include <string.h>
#include <stdint.h>

using namespace nvcuda;

// Problem constants
#define NN   32768

typedef __nv_bfloat16 bf16;

// ---------------- scratch (allocation-free: __device__ globals) ----------------
__device__ bf16 g_F0h [NN*512];  __device__ bf16 g_F0l [NN*512];
__device__ bf16 g_H1h [NN*512];  __device__ bf16 g_H1l [NN*512];
__device__ bf16 g_H2h [NN*512];  __device__ bf16 g_H2l [NN*512];
__device__ bf16 g_H3h [NN*512];  __device__ bf16 g_H3l [NN*512];
__device__ bf16 g_G1h [NN*512];  __device__ bf16 g_G1l [NN*512];
__device__ bf16 g_G2h [NN*512];  __device__ bf16 g_G2l [NN*512];
__device__ bf16 g_G3h [NN*512];  __device__ bf16 g_G3l [NN*512];
__device__ bf16 g_VG1h[NN*768];  __device__ bf16 g_VG1l[NN*768];
__device__ bf16 g_VG2h[NN*768];  __device__ bf16 g_VG2l[NN*768];
__device__ bf16 g_VG3h[NN*768];  __device__ bf16 g_VG3l[NN*768];
__device__ bf16 g_F0th[NN*512];  __device__ bf16 g_F0tl[NN*512];
// fp32 scratch
__device__ float g_V  [NN*768];
__device__ float g_Vt [NN*768];
__device__ float g_SL [NN*256];
__device__ float g_SR [NN*256];
__device__ float g_VL [NN*768];
__device__ float g_VR [NN*768];
__device__ float g_VO3[NN*768];

// converted weights: [Nc][K] bf16 (n-major rows, k contiguous), alpha folded in
#define WTOTAL 1966080
__device__ bf16 g_Whi[WTOTAL];
__device__ bf16 g_Wlo[WTOTAL];

// ---------------- helpers ----------------
__device__ __forceinline__ uint32_t s2u(const void* p) {
    return (uint32_t)__cvta_generic_to_shared(p);
}
__device__ __forceinline__ void cp_async16(uint32_t smem_addr, const void* gptr) {
    asm volatile("cp.async.cg.shared.global [%0], [%1], 16;"
                 :: "r"(smem_addr), "l"(gptr) : "memory");
}
#define CP_COMMIT()   asm volatile("cp.async.commit_group;" ::: "memory")
#define CP_WAIT_ALL() asm volatile("cp.async.wait_group 0;" ::: "memory")

__device__ __forceinline__ void split_bf16(float v, bf16& h, bf16& l) {
    h = __float2bfloat16(v);
    l = __float2bfloat16(v - __bfloat162float(h));
}

// ---------------- wmma split-bf16 GEMM (template-specialized) ----------------
// C = act( (Ahi+Alo)[M,K] @ (Whi+Wlo)^T + bias + res )
// SPLIT_OUT: write Chi/Clo bf16 pair; else write Cf fp32.
// SMEM per stage: AH/AL/BH/BL [128][LDE=40] bf16 = 40960 B; 2 stages.
// grid = (Nc/128, M/128), 256 threads = 8 warps in 2(m) x 4(n).
#define LDE 40
#define STAGE_E 20480
#define GEMM_SMEM 81920

template<bool SPLIT_OUT, bool ACT, bool RES>
__global__ void __launch_bounds__(256, 2)
gemm_tc(const bf16* __restrict__ Ahi, const bf16* __restrict__ Alo, int lda,
        const bf16* __restrict__ Bhi, const bf16* __restrict__ Blo, int ldb,
        float* __restrict__ Cf, bf16* __restrict__ Chi, bf16* __restrict__ Clo,
        int ldc,
        const float* __restrict__ bias,
        const float* __restrict__ res, int ldres,
        int K)
{
    extern __shared__ __align__(16) bf16 smx[];

    const int tid  = threadIdx.x;
    const int wid  = tid >> 5;
    const int wm   = wid & 1;
    const int wn   = wid >> 1;
    const int block_m = blockIdx.y * 128;
    const int block_n = blockIdx.x * 128;

    wmma::fragment<wmma::accumulator, 16, 16, 16, float> acc[4][2];
#pragma unroll
    for (int mi = 0; mi < 4; ++mi)
#pragma unroll
        for (int ni = 0; ni < 2; ++ni)
            wmma::fill_fragment(acc[mi][ni], 0.0f);

    const int nk = K >> 5;

    auto CP_T = [&](int s, int k0) {
        uint32_t ah = s2u(smx) + s * (STAGE_E * 2);
        uint32_t al = ah + 10240;
        uint32_t bh = ah + 20480;
        uint32_t bl = ah + 30720;
#pragma unroll
        for (int it = 0; it < 2; ++it) {
            int id = it * 256 + tid, row = id >> 2, c = id & 3;
            uint32_t so = (uint32_t)(row * 80 + c * 16);
            size_t ao = (size_t)(block_m + row) * lda + k0 + c * 8;
            cp_async16(ah + so, Ahi + ao);
            cp_async16(al + so, Alo + ao);
            size_t bo = (size_t)(block_n + row) * ldb + k0 + c * 8;
            cp_async16(bh + so, Bhi + bo);
            cp_async16(bl + so, Blo + bo);
        }
    };
    auto COMPUTE = [&](int s) {
        const bf16* AH = smx + s * STAGE_E;
        const bf16* AL = AH + 5120;
        const bf16* BH = AH + 10240;
        const bf16* BL = AH + 15360;
#pragma unroll
        for (int ks = 0; ks < 2; ++ks) {
            const int kofs = ks * 16;
            wmma::fragment<wmma::matrix_a, 16, 16, 16, bf16, wmma::row_major> fah[4], fal[4];
#pragma unroll
            for (int mi = 0; mi < 4; ++mi) {
                wmma::load_matrix_sync(fah[mi], AH + (wm * 64 + mi * 16) * LDE + kofs, LDE);
                wmma::load_matrix_sync(fal[mi], AL + (wm * 64 + mi * 16) * LDE + kofs, LDE);
            }
#pragma unroll
            for (int ni = 0; ni < 2; ++ni) {
                wmma::fragment<wmma::matrix_b, 16, 16, 16, bf16, wmma::col_major> fbh, fbl;
                wmma::load_matrix_sync(fbh, BH + (wn * 32 + ni * 16) * LDE + kofs, LDE);
                wmma::load_matrix_sync(fbl, BL + (wn * 32 + ni * 16) * LDE + kofs, LDE);
#pragma unroll
                for (int mi = 0; mi < 4; ++mi) {
                    wmma::mma_sync(acc[mi][ni], fah[mi], fbh, acc[mi][ni]);
                    wmma::mma_sync(acc[mi][ni], fah[mi], fbl, acc[mi][ni]);
                    wmma::mma_sync(acc[mi][ni], fal[mi], fbh, acc[mi][ni]);
                }
            }
        }
    };

    CP_T(0, 0);
    CP_COMMIT();
    CP_WAIT_ALL();
    __syncthreads();

    for (int it = 0; it < nk; ++it) {
        if (it + 1 < nk) {
            CP_T((it + 1) & 1, (it + 1) << 5);
            CP_COMMIT();
        }
        COMPUTE(it & 1);
        CP_WAIT_ALL();
        __syncthreads();
    }

    // ---- epilogue: two half-tile passes through SMEM ----
    float* sf = reinterpret_cast<float*>(smx);
    __syncthreads();
#pragma unroll
    for (int pass = 0; pass < 2; ++pass) {
        if (wm == pass) {
#pragma unroll
            for (int mi = 0; mi < 4; ++mi)
#pragma unroll
                for (int ni = 0; ni < 2; ++ni)
                    wmma::store_matrix_sync(sf + (mi * 16) * 128 + wn * 32 + ni * 16,
                                            acc[mi][ni], 128, wmma::mem_row_major);
        }
        __syncthreads();
        for (int i = tid; i < 2048; i += 256) {   // 64 rows x 32 float4
            int r = i >> 5, c4 = (i & 31) * 4;
            float4 v = *reinterpret_cast<float4*>(sf + r * 128 + c4);
            int row = block_m + pass * 64 + r;
            int col = block_n + c4;
            float vv[4] = {v.x, v.y, v.z, v.w};
#pragma unroll
            for (int j = 0; j < 4; ++j) {
                float t = vv[j];
                if (bias) t += bias[col + j];
                if (RES)  t += res[(size_t)row * ldres + col + j];
                if (ACT)  t = t / (1.0f + __expf(-t));
                vv[j] = t;
            }
            if (SPLIT_OUT) {
                bf16 h[4], l[4];
#pragma unroll
                for (int j = 0; j < 4; ++j) split_bf16(vv[j], h[j], l[j]);
                *reinterpret_cast<uint2*>(Chi + (size_t)row * ldc + col) =
                    *reinterpret_cast<uint2*>(h);
                *reinterpret_cast<uint2*>(Clo + (size_t)row * ldc + col) =
                    *reinterpret_cast<uint2*>(l);
            } else {
                float4 o; o.x = vv[0]; o.y = vv[1]; o.z = vv[2]; o.w = vv[3];
                *reinterpret_cast<float4*>(Cf + (size_t)row * ldc + col) = o;
            }
        }
        __syncthreads();
    }
}

// ---------------- batched weight conversion ----------------------------------
__global__ void convert_w6(const float* w0, const float* w1, const float* w2,
                           const float* w3, const float* w4, const float* w5,
                           bf16* __restrict__ hi, bf16* __restrict__ lo,
                           int K, int Nc, float scale, int stride_e)
{
    int per = K * Nc;
    int gidx = blockIdx.x * blockDim.x + threadIdx.x;
    if (gidx >= 6 * per) return;
    int which = gidx / per;
    int idx = gidx - which * per;
    const float* W;
    switch (which) {
        case 0: W = w0; break;
        case 1: W = w1; break;
        case 2: W = w2; break;
        case 3: W = w3; break;
        case 4: W = w4; break;
        default: W = w5; break;
    }
    int n = idx / K, k = idx % K;
    float v = W[(size_t)k * Nc + n] * scale;
    bf16 h, l; split_bf16(v, h, l);
    size_t o = (size_t)which * stride_e + idx;
    hi[o] = h;
    lo[o] = l;
}

// ---------------- elementwise kernels (R15-verified) ----------------
__global__ void prep_kernel(const float* __restrict__ x,
                            bf16* __restrict__ F0h, bf16* __restrict__ F0l,
                            float* __restrict__ V)
{
    const int n = blockIdx.x;
    const int u = threadIdx.x;
    const float* xr = x + (size_t)n * 1024;
    float s  = xr[u];
    float v0 = xr[256 + 3 * u + 0];
    float v1 = xr[256 + 3 * u + 1];
    float v2 = xr[256 + 3 * u + 2];
    float nv = sqrtf(v0 * v0 + v1 * v1 + v2 * v2 + 1e-12f);
    bf16 h, l;
    split_bf16(s,  h, l); F0h[(size_t)n * 512 + u] = h;        F0l[(size_t)n * 512 + u] = l;
    split_bf16(nv, h, l); F0h[(size_t)n * 512 + 256 + u] = h;  F0l[(size_t)n * 512 + 256 + u] = l;
    size_t vb = ((size_t)3 * n) * 256 + u;
    V[vb]       = v0;
    V[vb + 256] = v1;
    V[vb + 512] = v2;
}

__global__ void gate_kernel(const float* __restrict__ V,
                            const bf16* __restrict__ Gh, const bf16* __restrict__ Gl,
                            bf16* __restrict__ VGh, bf16* __restrict__ VGl)
{
    size_t idx = (size_t)blockIdx.x * blockDim.x + threadIdx.x;
    int u = (int)(idx & 255);
    size_t r = idx >> 8;
    size_t n = r / 3;
    size_t go = n * 512 + 256 + u;
    float g = __bfloat162float(Gh[go]) + __bfloat162float(Gl[go]);
    float v = V[idx] * g;
    bf16 h, l; split_bf16(v, h, l);
    VGh[idx] = h;
    VGl[idx] = l;
}

__global__ void tp_kernel(const float* __restrict__ SL, const float* __restrict__ VL,
                          const float* __restrict__ SR, const float* __restrict__ VR,
                          const float* __restrict__ x, const float* __restrict__ V,
                          const float* __restrict__ tpw,
                          bf16* __restrict__ F0th, bf16* __restrict__ F0tl,
                          float* __restrict__ Vt)
{
    const int n = blockIdx.x;
    const int u = threadIdx.x;
    const size_t b256 = (size_t)n * 256 + u;
    const size_t b512 = (size_t)n * 512 + u;
    const size_t vb   = ((size_t)3 * n) * 256 + u;

    float s1 = SL[b256], s2 = SR[b256];
    float ax = VL[vb], ay = VL[vb + 256], az = VL[vb + 512];
    float bx = VR[vb], by = VR[vb + 256], bz = VR[vb + 512];
    float w0 = tpw[u], w1 = tpw[256 + u], w2 = tpw[512 + u],
          w3 = tpw[768 + u], w4 = tpw[1024 + u];

    const float A0 = 0.44721359549995793f;
    const float A1 = 0.77459666924148340f;
    const float I3 = 0.57735026918962576f;
    const float I6 = 0.40824829046386302f;

    float dot = ax * bx + ay * by + az * bz;
    float t0 = A0 * (w0 * s1 * s2 + w3 * I3 * dot) + x[(size_t)n * 1024 + u];

    float cx = ay * bz - az * by;
    float cy = az * bx - ax * bz;
    float cz = ax * by - ay * bx;
    float k1 = A1 * I3 * w1 * s1;
    float k2 = A1 * I3 * w2 * s2;
    float k4 = A1 * I6 * w4;
    float tx = k1 * bx + k2 * ax + k4 * cx + V[vb];
    float ty = k1 * by + k2 * ay + k4 * cy + V[vb + 256];
    float tz = k1 * bz + k2 * az + k4 * cz + V[vb + 512];

    float nv = sqrtf(tx * tx + ty * ty + tz * tz + 1e-12f);
    bf16 h, l;
    split_bf16(t0, h, l); F0th[b512] = h;        F0tl[b512] = l;
    split_bf16(nv, h, l); F0th[b512 + 256] = h;  F0tl[b512 + 256] = l;
    Vt[vb]       = tx;
    Vt[vb + 256] = ty;
    Vt[vb + 512] = tz;
}

__global__ void final_kernel(const float* __restrict__ VO3,
                             const float* __restrict__ old_fii,
                             float* __restrict__ out)
{
    size_t idx = (size_t)blockIdx.x * blockDim.x + threadIdx.x;
    size_t n = idx / 768;
    int j = (int)(idx % 768);
    int u = j / 3;
    int i = j % 3;
    size_t o = n * 1024 + 256 + j;
    out[o] = old_fii[o] + VO3[((size_t)3 * n + i) * 256 + u];
}

// ---------------- host launch helpers ----------------
template<bool SPLIT_OUT, bool ACT, bool RES>
static inline void launch_tc(const bf16* ah, const bf16* al, int lda,
                             const bf16* bh, const bf16* bl, int ldb,
                             float* Cf, bf16* Chi, bf16* Clo, int ldc,
                             const float* bias, const float* res, int ldres,
                             int M, int Nc, int K)
{
    dim3 grid(Nc / 128, M / 128);
    gemm_tc<SPLIT_OUT, ACT, RES><<<grid, 256, GEMM_SMEM>>>(
        ah, al, lda, bh, bl, ldb, Cf, Chi, Clo, ldc, bias, res, ldres, K);
}

extern "C" void kernel_launch(void* const* d_in, const int* in_sizes, int n_in,
                              void* d_out, int out_size)
{
    const float* x       = (const float*)d_in[0];
    const float* old_fii = (const float*)d_in[1];
    const float* ng1_w1 = (const float*)d_in[2];
    const float* ng1_b1 = (const float*)d_in[3];
    const float* ng1_w2 = (const float*)d_in[4];
    const float* ng1_b2 = (const float*)d_in[5];
    const float* ng2_w1 = (const float*)d_in[6];
    const float* ng2_b1 = (const float*)d_in[7];
    const float* ng2_w2 = (const float*)d_in[8];
    const float* ng2_b2 = (const float*)d_in[9];
    const float* ngo_w1 = (const float*)d_in[10];
    const float* ngo_b1 = (const float*)d_in[11];
    const float* ngo_w2 = (const float*)d_in[12];
    const float* ngo_b2 = (const float*)d_in[13];
    const float* lin1_w0 = (const float*)d_in[14];
    const float* lin1_b0 = (const float*)d_in[15];
    const float* lin1_w1 = (const float*)d_in[16];
    const float* lin2_w0 = (const float*)d_in[17];
    const float* lin2_b0 = (const float*)d_in[18];
    const float* lin2_w1 = (const float*)d_in[19];
    const float* lin3_w0 = (const float*)d_in[20];
    const float* lin3_b0 = (const float*)d_in[21];
    const float* lin3_w1 = (const float*)d_in[22];
    const float* tp_w    = (const float*)d_in[23];
    float* out = (float*)d_out;

    cudaFuncSetAttribute(gemm_tc<true,  true,  false>, cudaFuncAttributeMaxDynamicSharedMemorySize, GEMM_SMEM);
    cudaFuncSetAttribute(gemm_tc<true,  false, false>, cudaFuncAttributeMaxDynamicSharedMemorySize, GEMM_SMEM);
    cudaFuncSetAttribute(gemm_tc<false, false, false>, cudaFuncAttributeMaxDynamicSharedMemorySize, GEMM_SMEM);
    cudaFuncSetAttribute(gemm_tc<false, false, true >, cudaFuncAttributeMaxDynamicSharedMemorySize, GEMM_SMEM);

    bf16 *F0h,*F0l,*H1h,*H1l,*H2h,*H2l,*H3h,*H3l,*G1h,*G1l,*G2h,*G2l,*G3h,*G3l,
         *VG1h,*VG1l,*VG2h,*VG2l,*VG3h,*VG3l,*F0th,*F0tl,*Whi,*Wlo;
    float *V,*Vt,*SL,*SR,*VL,*VR,*VO3;
    cudaGetSymbolAddress((void**)&F0h,  g_F0h);  cudaGetSymbolAddress((void**)&F0l,  g_F0l);
    cudaGetSymbolAddress((void**)&H1h,  g_H1h);  cudaGetSymbolAddress((void**)&H1l,  g_H1l);
    cudaGetSymbolAddress((void**)&H2h,  g_H2h);  cudaGetSymbolAddress((void**)&H2l,  g_H2l);
    cudaGetSymbolAddress((void**)&H3h,  g_H3h);  cudaGetSymbolAddress((void**)&H3l,  g_H3l);
    cudaGetSymbolAddress((void**)&G1h,  g_G1h);  cudaGetSymbolAddress((void**)&G1l,  g_G1l);
    cudaGetSymbolAddress((void**)&G2h,  g_G2h);  cudaGetSymbolAddress((void**)&G2l,  g_G2l);
    cudaGetSymbolAddress((void**)&G3h,  g_G3h);  cudaGetSymbolAddress((void**)&G3l,  g_G3l);
    cudaGetSymbolAddress((void**)&VG1h, g_VG1h); cudaGetSymbolAddress((void**)&VG1l, g_VG1l);
    cudaGetSymbolAddress((void**)&VG2h, g_VG2h); cudaGetSymbolAddress((void**)&VG2l, g_VG2l);
    cudaGetSymbolAddress((void**)&VG3h, g_VG3h); cudaGetSymbolAddress((void**)&VG3l, g_VG3l);
    cudaGetSymbolAddress((void**)&F0th, g_F0th); cudaGetSymbolAddress((void**)&F0tl, g_F0tl);
    cudaGetSymbolAddress((void**)&Whi,  g_Whi);  cudaGetSymbolAddress((void**)&Wlo,  g_Wlo);
    cudaGetSymbolAddress((void**)&V,    g_V);
    cudaGetSymbolAddress((void**)&Vt,   g_Vt);
    cudaGetSymbolAddress((void**)&SL,   g_SL);
    cudaGetSymbolAddress((void**)&SR,   g_SR);
    cudaGetSymbolAddress((void**)&VL,   g_VL);
    cudaGetSymbolAddress((void**)&VR,   g_VR);
    cudaGetSymbolAddress((void**)&VO3,  g_VO3);

    const int OB = 262144, OS = 65536;
    const int o_ng1w1 = 0,      o_ng2w1 = OB,     o_ng1w2 = 2*OB,
              o_ng2w2 = 3*OB,   o_ngow1 = 4*OB,   o_ngow2 = 5*OB;
    const int o_l1w0 = 6*OB,        o_l1w1 = 6*OB + OS,   o_l2w0 = 6*OB + 2*OS,
              o_l2w1 = 6*OB + 3*OS, o_l3w0 = 6*OB + 4*OS, o_l3w1 = 6*OB + 5*OS;

    const float inv16 = 0.0625f;

    {
        const int T = 256;
        int nb = (6 * 512 * 512 + T - 1) / T;
        convert_w6<<<nb, T>>>(ng1_w1, ng2_w1, ng1_w2, ng2_w2, ngo_w1, ngo_w2,
                              Whi, Wlo, 512, 512, 1.f, OB);
        int ns = (6 * 256 * 256 + T - 1) / T;
        convert_w6<<<ns, T>>>(lin1_w0, lin1_w1, lin2_w0, lin2_w1, lin3_w0, lin3_w1,
                              Whi + 6 * OB, Wlo + 6 * OB, 256, 256, inv16, OS);
    }

    prep_kernel<<<NN, 256>>>(x, F0h, F0l, V);

    // Stage 2: NormGate MLPs (left/right) — hi/lo outputs
    launch_tc<true, true, false>(F0h, F0l, 512, Whi + o_ng1w1, Wlo + o_ng1w1, 512,
                                 nullptr, H1h, H1l, 512, ng1_b1, nullptr, 0, NN, 512, 512);
    launch_tc<true, true, false>(F0h, F0l, 512, Whi + o_ng2w1, Wlo + o_ng2w1, 512,
                                 nullptr, H2h, H2l, 512, ng2_b1, nullptr, 0, NN, 512, 512);
    launch_tc<true, false, false>(H1h, H1l, 512, Whi + o_ng1w2, Wlo + o_ng1w2, 512,
                                  nullptr, G1h, G1l, 512, ng1_b2, nullptr, 0, NN, 512, 512);
    launch_tc<true, false, false>(H2h, H2l, 512, Whi + o_ng2w2, Wlo + o_ng2w2, 512,
                                  nullptr, G2h, G2l, 512, ng2_b2, nullptr, 0, NN, 512, 512);

    // Stage 3: gate vectors (hi/lo out)
    gate_kernel<<<NN * 3, 256>>>(V, G1h, G1l, VG1h, VG1l);
    gate_kernel<<<NN * 3, 256>>>(V, G2h, G2l, VG2h, VG2l);

    // Stage 4: irrep linears (fp32 out for tp)
    launch_tc<false, false, false>(G1h,  G1l,  512, Whi + o_l1w0, Wlo + o_l1w0, 256,
                                   SL, nullptr, nullptr, 256, lin1_b0, nullptr, 0, NN,     256, 256);
    launch_tc<false, false, false>(VG1h, VG1l, 256, Whi + o_l1w1, Wlo + o_l1w1, 256,
                                   VL, nullptr, nullptr, 256, nullptr, nullptr, 0, 3 * NN, 256, 256);
    launch_tc<false, false, false>(G2h,  G2l,  512, Whi + o_l2w0, Wlo + o_l2w0, 256,
                                   SR, nullptr, nullptr, 256, lin2_b0, nullptr, 0, NN,     256, 256);
    launch_tc<false, false, false>(VG2h, VG2l, 256, Whi + o_l2w1, Wlo + o_l2w1, 256,
                                   VR, nullptr, nullptr, 256, nullptr, nullptr, 0, 3 * NN, 256, 256);

    // Stage 5: tensor product + resnet (F0t hi/lo, Vt fp32)
    tp_kernel<<<NN, 256>>>(SL, VL, SR, VR, x, V, tp_w, F0th, F0tl, Vt);

    // Stage 6: output NormGate
    launch_tc<true, true, false>(F0th, F0tl, 512, Whi + o_ngow1, Wlo + o_ngow1, 512,
                                 nullptr, H3h, H3l, 512, ngo_b1, nullptr, 0, NN, 512, 512);
    launch_tc<true, false, false>(H3h,  H3l,  512, Whi + o_ngow2, Wlo + o_ngow2, 512,
                                  nullptr, G3h, G3l, 512, ngo_b2, nullptr, 0, NN, 512, 512);
    gate_kernel<<<NN * 3, 256>>>(Vt, G3h, G3l, VG3h, VG3l);

    // Stage 7: final irrep linear + old_fii residual
    launch_tc<false, false, true>(G3h,  G3l,  512, Whi + o_l3w0, Wlo + o_l3w0, 256,
                                  out, nullptr, nullptr, 1024, lin3_b0, old_fii, 1024, NN, 256, 256);
    launch_tc<false, false, false>(VG3h, VG3l, 256, Whi + o_l3w1, Wlo + o_l3w1, 256,
                                   VO3, nullptr, nullptr, 256, nullptr, nullptr, 0, 3 * NN, 256, 256);
    final_kernel<<<NN * 3, 256>>>(VO3, old_fii, out);
}